// round 8
// baseline (speedup 1.0000x reference)
#include <cuda_runtime.h>
#include <cstdint>

// Problem constants (fixed by setup_inputs)
#define NB 4
#define CC 128
#define HH 160
#define WW 320
#define DD 48

#define WT   128            // w-tile per CTA
#define RT   (WT + 48)      // right tile width incl. disparity halo = 176
#define CHS  16             // channels per pipeline stage
#define NSTG (CC / CHS)     // 8 stages
#define NTHR 128            // 4 warps: {h-row pair} x {d half: 24 disparities}
#define NROW 2              // h rows per CTA

// stage: 2 rows * CHS * (WT + RT) floats = 9728 floats = 38912 B; x2 buffers = 77824 B
#define STAGE_FLOATS (NROW * CHS * (WT + RT))
#define SMEM_FLOATS  (2 * STAGE_FLOATS)
#define LS_FLOATS    (NROW * CHS * WT)       // offset of Rs within a stage

__device__ __forceinline__ uint32_t smem_u32(const void* p) {
    return (uint32_t)__cvta_generic_to_shared(p);
}
// 16B async copy, global->shared, zero-fill when bytes==0 (halo padding).
__device__ __forceinline__ void cp16(uint32_t dst, const void* src, int bytes) {
    asm volatile("cp.async.cg.shared.global [%0], [%1], 16, %2;"
                 :: "r"(dst), "l"(src), "r"(bytes));
}

__global__ void __launch_bounds__(NTHR, 2)
cost_volume_kernel(const float* __restrict__ left,
                   const float* __restrict__ right,
                   float* __restrict__ out)
{
    extern __shared__ float smem[];

    const int tid  = threadIdx.x;
    const int lane = tid & 31;
    const int warp = tid >> 5;            // 0..3
    const int hsel = warp >> 1;           // which of the 2 h rows
    const int d0   = (warp & 1) * 24;     // disparity half
    const int w0   = blockIdx.x * WT;     // 0,128,256 (last tile partial)
    const int h0   = blockIdx.y * NROW;   // 0..158, even
    const int n    = blockIdx.z;

    // Rs[row][c][i] holds global w = w0-48+i. acc[dj][wi] needs R at
    // w0+4*lane+wi-(d0+dj)  ->  i = 4*lane - d0 + 48 + wi - dj,
    // dj in [0,24), wi in [0,4)  ->  i in [ib+1, ib+27] with:
    const int ib = 4 * lane - d0 + 24;    // multiple of 4, in [0,148]

    const size_t chan_stride = (size_t)HH * WW;
    const float* lrow = left  + (size_t)n * CC * chan_stride + (size_t)h0 * WW;
    const float* rrow = right + (size_t)n * CC * chan_stride + (size_t)h0 * WW;

    // ---- async prefetch of one stage (2 rows x CHS channels) into `buf` ----
    auto prefetch = [&](int c0, float* buf) {
        float* Ls = buf;               // [NROW][CHS][WT]
        float* Rs = buf + LS_FLOATS;   // [NROW][CHS][RT]
        const float* lb = lrow + (size_t)c0 * chan_stride;
        const float* rb = rrow + (size_t)c0 * chan_stride;
        // L: NROW*CHS*WT/4 = 1024 float4 -> 8 per thread
        #pragma unroll
        for (int it = 0; it < 8; it++) {
            int idx = tid + it * NTHR;          // 0..1023
            int r2  = idx >> 9;                 // row (512 float4 per row)
            int c   = (idx >> 5) & (CHS - 1);
            int wq  = (idx & 31) << 2;
            int gw  = w0 + wq;
            bool ok = (gw < WW);
            const float* src = ok ? (lb + (size_t)c * chan_stride + (size_t)r2 * WW + gw) : lb;
            cp16(smem_u32(Ls + ((r2 * CHS + c) * WT + wq)), src, ok ? 16 : 0);
        }
        // R: NROW*CHS*RT/4 = 1408 float4 -> 11 per thread
        #pragma unroll
        for (int it = 0; it < 11; it++) {
            int idx = tid + it * NTHR;          // 0..1407
            int r2  = idx / (CHS * (RT / 4));   // /704
            int rem = idx - r2 * (CHS * (RT / 4));
            int c   = rem / (RT / 4);           // /44
            int wq  = (rem - c * (RT / 4)) << 2;
            int gw  = w0 - 48 + wq;
            bool ok = (gw >= 0) && (gw < WW);
            const float* src = ok ? (rb + (size_t)c * chan_stride + (size_t)r2 * WW + gw) : rb;
            cp16(smem_u32(Rs + ((r2 * CHS + c) * RT + wq)), src, ok ? 16 : 0);
        }
        asm volatile("cp.async.commit_group;");
    };

    float acc[24][4];
    #pragma unroll
    for (int j = 0; j < 24; j++)
        #pragma unroll
        for (int i = 0; i < 4; i++) acc[j][i] = 0.0f;

    prefetch(0, smem);

    for (int s = 0; s < NSTG; s++) {
        float* cur = smem + (s & 1) * STAGE_FLOATS;
        if (s + 1 < NSTG) {
            prefetch((s + 1) * CHS, smem + ((s + 1) & 1) * STAGE_FLOATS);
            asm volatile("cp.async.wait_group 1;");   // stage s complete
        } else {
            asm volatile("cp.async.wait_group 0;");
        }
        __syncthreads();

        // ---- FFMA mainloop: per channel 8 LDS.128 -> 96 FMAs ----
        const float* lp = cur + hsel * (CHS * WT) + 4 * lane;
        const float* rp = cur + LS_FLOATS + hsel * (CHS * RT) + ib;
        #pragma unroll 2
        for (int c = 0; c < CHS; c++) {
            float4 lv = *(const float4*)(lp + c * WT);
            float lw[4] = { lv.x, lv.y, lv.z, lv.w };
            float r[28];
            #pragma unroll
            for (int k = 0; k < 7; k++) {
                float4 rv = *(const float4*)(rp + c * RT + 4 * k);
                r[4*k+0] = rv.x; r[4*k+1] = rv.y; r[4*k+2] = rv.z; r[4*k+3] = rv.w;
            }
            #pragma unroll
            for (int dj = 0; dj < 24; dj++)
                #pragma unroll
                for (int wi = 0; wi < 4; wi++)
                    acc[dj][wi] = fmaf(lw[wi], r[wi - dj + 24], acc[dj][wi]);
        }
        __syncthreads();   // compute done before next prefetch overwrites buffer
    }

    // ---- store: 24 float4 per thread; last tile guarded ----
    const int gw = w0 + 4 * lane;
    const int h  = h0 + hsel;
    if (gw < WW) {
        #pragma unroll
        for (int dj = 0; dj < 24; dj++) {
            int d = d0 + dj;
            float4 v = make_float4(acc[dj][0], acc[dj][1], acc[dj][2], acc[dj][3]);
            *(float4*)(out + (((size_t)(n * DD + d) * HH + h) * WW + gw)) = v;
        }
    }
}

extern "C" void kernel_launch(void* const* d_in, const int* in_sizes, int n_in,
                              void* d_out, int out_size)
{
    const float* left  = (const float*)d_in[0];
    const float* right = (const float*)d_in[1];
    float* out = (float*)d_out;

    cudaFuncSetAttribute(cost_volume_kernel,
                         cudaFuncAttributeMaxDynamicSharedMemorySize,
                         SMEM_FLOATS * (int)sizeof(float));

    dim3 grid((WW + WT - 1) / WT, HH / NROW, NB);   // (3, 80, 4)
    cost_volume_kernel<<<grid, NTHR, SMEM_FLOATS * sizeof(float)>>>(left, right, out);
}